// round 11
// baseline (speedup 1.0000x reference)
#include <cuda_runtime.h>
#include <cuda_fp16.h>
#include <cstddef>

// Problem constants (fixed shapes from reference setup_inputs)
constexpr int BB = 4;      // batch
constexpr int GG = 9;      // groups
constexpr int DD = 16;     // channels per group
constexpr int CC = GG * DD;  // 144
constexpr int NN = 16384;  // points
constexpr int KK = 16;     // knn neighbors

constexpr int PTS = BB * GG * NN;  // 589824 points total
constexpr int JP  = 5;             // group-pair slices: {0,1}{2,3}{4,5}{6,7}{8,pad}
constexpr int CT_PAD = 12;         // cent_t row pad: 48B rows keep 16B alignment
constexpr int NB  = 32;            // points (n) per attn block
static_assert((PTS) % 256 == 0, "exact transpose grid");
static_assert(NN % NB == 0, "exact attn tiling");
static_assert((BB * NN * KK) % 256 == 0, "exact scatter grid");
static_assert((BB * NN) % 256 == 0, "exact finalize grid");
static_assert((BB * NN * CT_PAD) % (4 * 256) == 0, "exact zero grid");

// Scratch: fp16 k/v for a PAIR of groups per 128B line.
// Line (b, j, n): 8 slots of 16B; slot s = (group-half gh = s>>2, quad q = s&3):
//   { half2(k4q,k4q+1), half2(k4q+2,k4q+3), half2(v4q,v4q+1), half2(v4q+2,v4q+3) }
// for group g = 2j + gh. j=4 upper half is padding (zero-initialized, never
// written) so inactive lanes read zeros.
__device__ uint4 g_kv[(size_t)BB * JP * NN * 8];
// Softmax weights, layout [b][n][g][k] (contiguous 16 floats per (b,n,g))
__device__ float g_w[(size_t)BB * NN * GG * KK];
// Point-major centrality accumulator: [b][m][12] (g in 0..8, rest padding)
__device__ float g_ct[(size_t)BB * NN * CT_PAD];

// ---------------------------------------------------------------------------
// Zero kernel for g_ct (atomics accumulate into it each replay)
// ---------------------------------------------------------------------------
__global__ void zero_ct_kernel() {
    int i = blockIdx.x * blockDim.x + threadIdx.x;
    reinterpret_cast<float4*>(g_ct)[i] = make_float4(0.f, 0.f, 0.f, 0.f);
}

// ---------------------------------------------------------------------------
// Transpose kernel: (B, C, N) fp32 channel-major -> fp16 pair-of-groups
// 128B lines. Thread per (b, g, n): writes its 64B half of line (b, g>>1, n).
// ---------------------------------------------------------------------------
__global__ void transpose_kernel(const float* __restrict__ qk,
                                 const float* __restrict__ val) {
    int p = blockIdx.x * blockDim.x + threadIdx.x;
    if (p >= PTS) return;
    int n  = p % NN;
    int bg = p / NN;
    int g  = bg % GG;
    int b  = bg / GG;

    size_t src_off = ((size_t)b * CC + (size_t)g * DD) * NN + n;
    const float* __restrict__ qs = qk + src_off;
    const float* __restrict__ vs = val + src_off;

    float tq[DD], tv[DD];
#pragma unroll
    for (int dd = 0; dd < DD; dd++) {
        tq[dd] = qs[(size_t)dd * NN];
        tv[dd] = vs[(size_t)dd * NN];
    }

    // Destination: line (b, j=g>>1, n), half gh=g&1 (4 uint4 slots)
    uint4* dst = g_kv + (((size_t)(b * JP + (g >> 1)) * NN + n) * 8) + (g & 1) * 4;
#pragma unroll
    for (int q = 0; q < 4; q++) {
        __half2 k01 = __floats2half2_rn(tq[4*q+0], tq[4*q+1]);
        __half2 k23 = __floats2half2_rn(tq[4*q+2], tq[4*q+3]);
        __half2 v01 = __floats2half2_rn(tv[4*q+0], tv[4*q+1]);
        __half2 v23 = __floats2half2_rn(tv[4*q+2], tv[4*q+3]);
        dst[q] = make_uint4(*reinterpret_cast<unsigned int*>(&k01),
                            *reinterpret_cast<unsigned int*>(&k23),
                            *reinterpret_cast<unsigned int*>(&v01),
                            *reinterpret_cast<unsigned int*>(&v23));
    }
}

// ---------------------------------------------------------------------------
// Main attention kernel. Block = one (b, j) x 32 consecutive n.
// 8 lanes per (n): lane s = (gh = s>>2 selecting group g = 2j+gh,
// vq = s&3 selecting channel quad). Gathers: ONE LDG.128 per lane per
// neighbor; 8 lanes cover the full 128B pair-line.
// q and feat go through shared memory so global transfers are n-major
// coalesced 128B rows (1 wavefront each) instead of per-lane strided.
// smem tile [32ch][33] padded: bank = (ch + n) % 32 -> conflict-free for
// both the staged (row, lane) phase and the compute (s, nl) phase.
// ---------------------------------------------------------------------------
__global__ void __launch_bounds__(256, 4)
attn_kernel(const float* __restrict__ qk,
            const int* __restrict__ idx,
            float* __restrict__ out) {
    __shared__ float tile[NB * 33];   // 4224B: q staging, then feat staging

    const int tid = threadIdx.x;
    const int bj  = blockIdx.x / (NN / NB);       // b*JP + j
    const int n0  = (blockIdx.x % (NN / NB)) * NB;
    const int j   = bj % JP;
    const int b   = bj / JP;
    const int lane = tid & 31;
    const int wrow = tid >> 5;        // 0..7

    // ---- Stage q: 32 channel-rows x 32 n, coalesced 128B loads ----
    // Channel c_out = 32*j + ch; for j=4 only ch<16 exists (clamp reads).
#pragma unroll
    for (int i = 0; i < 4; i++) {
        int ch = wrow + 8 * i;                     // 0..31
        int chc = (j == 4) ? (ch & 15) : ch;       // clamp OOB for j=4
        tile[ch * 33 + lane] =
            qk[((size_t)b * CC + 32 * j + chc) * NN + n0 + lane];
    }
    __syncthreads();

    // ---- Compute ----
    const int s  = tid & 7;           // slot lane
    const int nl = (tid >> 3) & 31;   // local n
    const int n  = n0 + nl;
    const int gh = s >> 2;
    const int vq = s & 3;
    const int g  = 2 * j + gh;
    const bool active = (g < GG);

    const int chb = gh * 16 + 4 * vq;
    float q0 = tile[(chb + 0) * 33 + nl];
    float q1 = tile[(chb + 1) * 33 + nl];
    float q2 = tile[(chb + 2) * 33 + nl];
    float q3 = tile[(chb + 3) * 33 + nl];

    // Neighbor indices: 16 ints contiguous (64B), broadcast in 8-lane cluster
    const int4* __restrict__ ip =
        reinterpret_cast<const int4*>(idx + ((size_t)b * NN + n) * KK);
    int4 i0 = ip[0], i1 = ip[1], i2 = ip[2], i3 = ip[3];
    int nb[KK] = {i0.x, i0.y, i0.z, i0.w,
                  i1.x, i1.y, i1.z, i1.w,
                  i2.x, i2.y, i2.z, i2.w,
                  i3.x, i3.y, i3.z, i3.w};

    const uint4* __restrict__ kvline = g_kv + (size_t)bj * NN * 8 + s;

    float e_mine[4];
    float sum = 0.0f;
    float a0 = 0.0f, a1 = 0.0f, a2 = 0.0f, a3 = 0.0f;
#pragma unroll
    for (int k = 0; k < KK; k++) {
        uint4 raw = kvline[(size_t)nb[k] * 8];
        float2 k01 = __half22float2(*reinterpret_cast<__half2*>(&raw.x));
        float2 k23 = __half22float2(*reinterpret_cast<__half2*>(&raw.y));

        float d = q0 * k01.x + q1 * k01.y + q2 * k23.x + q3 * k23.y;
        d += __shfl_xor_sync(0xffffffffu, d, 1);
        d += __shfl_xor_sync(0xffffffffu, d, 2);  // full dot within 4-lane half

        float ev = __expf(d);                  // shift-free softmax numerator
        sum += ev;
        if ((k >> 2) == vq)                    // compile-time k -> cheap select
            e_mine[k & 3] = ev;

        float2 v01 = __half22float2(*reinterpret_cast<__half2*>(&raw.z));
        float2 v23 = __half22float2(*reinterpret_cast<__half2*>(&raw.w));
        a0 = fmaf(ev, v01.x, a0);
        a1 = fmaf(ev, v01.y, a1);
        a2 = fmaf(ev, v23.x, a2);
        a3 = fmaf(ev, v23.y, a3);
    }

    float inv = __fdividef(1.0f, sum);

    // w store (coalesced float4): W layout [b][n][g][k], lane vq covers
    // k = 4vq..4vq+3.
    if (active) {
        float4 w4 = make_float4(e_mine[0] * inv, e_mine[1] * inv,
                                e_mine[2] * inv, e_mine[3] * inv);
        float4* __restrict__ wp = reinterpret_cast<float4*>(
            g_w + (((size_t)b * NN + n) * GG + g) * KK);
        wp[vq] = w4;
    }

    // ---- Stage feat into smem (conflict-free), then coalesced stores ----
    __syncthreads();   // all q reads done; safe to overwrite tile
    tile[(chb + 0) * 33 + nl] = a0 * inv;
    tile[(chb + 1) * 33 + nl] = a1 * inv;
    tile[(chb + 2) * 33 + nl] = a2 * inv;
    tile[(chb + 3) * 33 + nl] = a3 * inv;
    __syncthreads();

#pragma unroll
    for (int i = 0; i < 4; i++) {
        int ch = wrow + 8 * i;                     // 0..31
        if (j == 4 && ch >= 16) continue;          // group 8 only has ch<16
        out[((size_t)b * CC + 32 * j + ch) * NN + n0 + lane] =
            tile[ch * 33 + lane];
    }
}

// ---------------------------------------------------------------------------
// Scatter kernel: thread per (b, n, k). Reads the 9 group-weights for this
// neighbor slot, then adds them to cent_t[b][m][0..8] with 2x red.v4 + 1
// scalar REDG (3 LSU lanes instead of 9).
// ---------------------------------------------------------------------------
__global__ void __launch_bounds__(256)
scatter_kernel(const int* __restrict__ idx) {
    int t  = blockIdx.x * blockDim.x + threadIdx.x;
    int k  = t & (KK - 1);
    int bn = t >> 4;                    // b*NN + n
    int b  = bn / NN;

    float w[GG];
#pragma unroll
    for (int g = 0; g < GG; g++)
        w[g] = g_w[((size_t)bn * GG + g) * KK + k];

    int m = idx[(size_t)bn * KK + k];

    float* row = g_ct + ((size_t)b * NN + m) * CT_PAD;
    asm volatile("red.global.add.v4.f32 [%0], {%1, %2, %3, %4};"
                 :: "l"(row), "f"(w[0]), "f"(w[1]), "f"(w[2]), "f"(w[3])
                 : "memory");
    asm volatile("red.global.add.v4.f32 [%0], {%1, %2, %3, %4};"
                 :: "l"(row + 4), "f"(w[4]), "f"(w[5]), "f"(w[6]), "f"(w[7])
                 : "memory");
    atomicAdd(row + 8, w[8]);
}

// ---------------------------------------------------------------------------
// Finalize kernel: cent_t (B, N, 12) -> cent (B, G, N); coalesced writes.
// ---------------------------------------------------------------------------
__global__ void finalize_kernel(float* __restrict__ out) {
    int t = blockIdx.x * blockDim.x + threadIdx.x;   // b*NN + m
    int b = t / NN;
    int m = t % NN;
    const float* __restrict__ row = g_ct + (size_t)t * CT_PAD;
    float* __restrict__ cent = out + (size_t)BB * CC * NN + (size_t)b * GG * NN + m;
#pragma unroll
    for (int g = 0; g < GG; g++)
        cent[(size_t)g * NN] = row[g];
}

extern "C" void kernel_launch(void* const* d_in, const int* in_sizes, int n_in,
                              void* d_out, int out_size) {
    const float* qk  = (const float*)d_in[0];   // queryandkey (B, C, N) f32
    const float* val = (const float*)d_in[1];   // value       (B, C, N) f32
    const int*   idx = (const int*)d_in[2];     // idx_knn     (B, N, K) i32
    float* out = (float*)d_out;                 // [feat (B,C,N) | cent (B,G,N)]

    const int threads = 256;

    zero_ct_kernel<<<(BB * NN * CT_PAD) / (4 * threads), threads>>>();
    transpose_kernel<<<PTS / threads, threads>>>(qk, val);
    attn_kernel<<<BB * JP * (NN / NB), threads>>>(qk, idx, out);
    scatter_kernel<<<(BB * NN * KK) / threads, threads>>>(idx);
    finalize_kernel<<<(BB * NN) / threads, threads>>>(out);
}

// round 13
// speedup vs baseline: 1.0780x; 1.0780x over previous
#include <cuda_runtime.h>
#include <cuda_fp16.h>
#include <cstddef>

// Problem constants (fixed shapes from reference setup_inputs)
constexpr int BB = 4;      // batch
constexpr int GG = 9;      // groups
constexpr int DD = 16;     // channels per group
constexpr int CC = GG * DD;  // 144
constexpr int NN = 16384;  // points
constexpr int KK = 16;     // knn neighbors

constexpr int PTS = BB * GG * NN;  // 589824 points total
constexpr int JP  = 5;             // group-pair slices: {0,1}{2,3}{4,5}{6,7}{8,pad}
constexpr int CT_PAD = 12;         // cent_t row pad: 48B rows keep 16B alignment
constexpr int CT_F4 = (BB * NN * CT_PAD) / 4;   // float4 count of g_ct
static_assert((PTS) % 256 == 0, "exact transpose grid");
static_assert(((size_t)BB * NN * JP * 8) % 256 == 0, "exact attn grid");
static_assert((BB * NN * KK) % 256 == 0, "exact scatter grid");
static_assert((BB * NN) % 256 == 0, "exact finalize grid");
static_assert(CT_F4 <= PTS, "zero folded into transpose covers g_ct");

// Scratch: fp16 k/v for a PAIR of groups per 128B line.
// Line (b, j, n): 8 slots of 16B; slot s = (group-half gh = s>>2, quad q = s&3):
//   { half2(k4q,k4q+1), half2(k4q+2,k4q+3), half2(v4q,v4q+1), half2(v4q+2,v4q+3) }
// for group g = 2j + gh. j=4 upper half is padding (zero-initialized, never
// written) so inactive lanes read zeros.
__device__ uint4 g_kv[(size_t)BB * JP * NN * 8];
// Softmax weights, fp16, layout [b][n][g][k] (16 halves per (b,n,g) = 32B)
__device__ __half g_w[(size_t)BB * NN * GG * KK];
// Point-major centrality accumulator: [b][m][12] (g in 0..8, rest padding)
__device__ float g_ct[(size_t)BB * NN * CT_PAD];

// ---------------------------------------------------------------------------
// Transpose kernel: (B, C, N) fp32 channel-major -> fp16 pair-of-groups
// 128B lines. Thread per (b, g, n). Also zeroes g_ct (folded zero kernel):
// first CT_F4 threads each clear one float4.
// ---------------------------------------------------------------------------
__global__ void transpose_kernel(const float* __restrict__ qk,
                                 const float* __restrict__ val) {
    int p = blockIdx.x * blockDim.x + threadIdx.x;
    if (p < CT_F4)
        reinterpret_cast<float4*>(g_ct)[p] = make_float4(0.f, 0.f, 0.f, 0.f);
    if (p >= PTS) return;
    int n  = p % NN;
    int bg = p / NN;
    int g  = bg % GG;
    int b  = bg / GG;

    size_t src_off = ((size_t)b * CC + (size_t)g * DD) * NN + n;
    const float* __restrict__ qs = qk + src_off;
    const float* __restrict__ vs = val + src_off;

    float tq[DD], tv[DD];
#pragma unroll
    for (int dd = 0; dd < DD; dd++) {
        tq[dd] = qs[(size_t)dd * NN];
        tv[dd] = vs[(size_t)dd * NN];
    }

    // Destination: line (b, j=g>>1, n), half gh=g&1 (4 uint4 slots)
    uint4* dst = g_kv + (((size_t)(b * JP + (g >> 1)) * NN + n) * 8) + (g & 1) * 4;
#pragma unroll
    for (int q = 0; q < 4; q++) {
        __half2 k01 = __floats2half2_rn(tq[4*q+0], tq[4*q+1]);
        __half2 k23 = __floats2half2_rn(tq[4*q+2], tq[4*q+3]);
        __half2 v01 = __floats2half2_rn(tv[4*q+0], tv[4*q+1]);
        __half2 v23 = __floats2half2_rn(tv[4*q+2], tv[4*q+3]);
        dst[q] = make_uint4(*reinterpret_cast<unsigned int*>(&k01),
                            *reinterpret_cast<unsigned int*>(&k23),
                            *reinterpret_cast<unsigned int*>(&v01),
                            *reinterpret_cast<unsigned int*>(&v23));
    }
}

// ---------------------------------------------------------------------------
// Main attention kernel (R10 structure): EIGHT lanes per (b, n, j) covering
// TWO groups. Lane s: group-half gh = s>>2 (g = 2j+gh), channel-quad vq = s&3.
// Per neighbor: ONE LDG.128 per lane; the 8 lanes cover the full 128B
// pair-line. Neighbor ids are loaded ONE int4 (4 ids) per chunk to cut
// live registers -> 5 blocks/SM (62.5% occ). Shift-free single-pass softmax;
// lane keeps only its own 4 weights (chunk kc == vq), stored as fp16 uint2.
// ---------------------------------------------------------------------------
__global__ void __launch_bounds__(256, 5)
attn_kernel(const float* __restrict__ qk,
            const int* __restrict__ idx,
            float* __restrict__ out) {
    int t  = blockIdx.x * blockDim.x + threadIdx.x;
    int s  = t & 7;           // slot lane
    int cn = t >> 3;          // cluster id = (b*JP + j)*NN + n
    int n  = cn % NN;
    int bj = cn / NN;
    int j  = bj % JP;
    int b  = bj / JP;
    int gh = s >> 2;
    int vq = s & 3;
    int g  = 2 * j + gh;
    bool active = (g < GG);
    int gq = active ? g : (GG - 1);   // clamp for safe q address

    // Self query quad (fp32, strided from the original channel-major array)
    const float* __restrict__ qbase =
        qk + ((size_t)b * CC + (size_t)gq * DD + 4 * vq) * NN + n;
    float q0 = qbase[0];
    float q1 = qbase[(size_t)NN];
    float q2 = qbase[(size_t)2 * NN];
    float q3 = qbase[(size_t)3 * NN];

    const int4* __restrict__ ip =
        reinterpret_cast<const int4*>(idx + ((size_t)b * NN + n) * KK);
    const uint4* __restrict__ kvline = g_kv + (size_t)bj * NN * 8 + s;

    float e_mine[4];
    float sum = 0.0f;
    float a0 = 0.0f, a1 = 0.0f, a2 = 0.0f, a3 = 0.0f;
#pragma unroll
    for (int kc = 0; kc < 4; kc++) {
        int4 iv = ip[kc];                     // 4 neighbor ids for this chunk
        int nbs[4] = {iv.x, iv.y, iv.z, iv.w};
        bool keep = (kc == vq);               // lane owns k = 4vq..4vq+3
#pragma unroll
        for (int k4 = 0; k4 < 4; k4++) {
            uint4 raw = kvline[(size_t)nbs[k4] * 8];
            float2 k01 = __half22float2(*reinterpret_cast<__half2*>(&raw.x));
            float2 k23 = __half22float2(*reinterpret_cast<__half2*>(&raw.y));

            float d = q0 * k01.x + q1 * k01.y + q2 * k23.x + q3 * k23.y;
            d += __shfl_xor_sync(0xffffffffu, d, 1);
            d += __shfl_xor_sync(0xffffffffu, d, 2);  // full dot in 4-lane half

            float ev = __expf(d);             // shift-free softmax numerator
            sum += ev;
            if (keep)
                e_mine[k4] = ev;

            float2 v01 = __half22float2(*reinterpret_cast<__half2*>(&raw.z));
            float2 v23 = __half22float2(*reinterpret_cast<__half2*>(&raw.w));
            a0 = fmaf(ev, v01.x, a0);
            a1 = fmaf(ev, v01.y, a1);
            a2 = fmaf(ev, v23.x, a2);
            a3 = fmaf(ev, v23.y, a3);
        }
    }

    float inv = __fdividef(1.0f, sum);

    if (active) {
        // Write feat quad in (B, C, N) layout.
        float* __restrict__ fo =
            out + ((size_t)b * CC + (size_t)g * DD + 4 * vq) * NN + n;
        fo[0]              = a0 * inv;
        fo[(size_t)NN]     = a1 * inv;
        fo[(size_t)2 * NN] = a2 * inv;
        fo[(size_t)3 * NN] = a3 * inv;

        // Store this lane's 4 normalized weights as fp16 (8B):
        // W layout [b][n][g][k]; lane vq covers k = 4vq..4vq+3.
        __half2 h01 = __floats2half2_rn(e_mine[0] * inv, e_mine[1] * inv);
        __half2 h23 = __floats2half2_rn(e_mine[2] * inv, e_mine[3] * inv);
        uint2 w2 = make_uint2(*reinterpret_cast<unsigned int*>(&h01),
                              *reinterpret_cast<unsigned int*>(&h23));
        uint2* __restrict__ wp = reinterpret_cast<uint2*>(
            g_w + (((size_t)b * NN + n) * GG + g) * KK);
        wp[vq] = w2;
    }
}

// ---------------------------------------------------------------------------
// Scatter kernel: thread per (b, n, k). Reads the 9 fp16 group-weights for
// this neighbor slot, then adds them to cent_t[b][m][0..8] with 2x red.v4 +
// 1 scalar REDG (3 LSU lanes instead of 9).
// ---------------------------------------------------------------------------
__global__ void __launch_bounds__(256)
scatter_kernel(const int* __restrict__ idx) {
    int t  = blockIdx.x * blockDim.x + threadIdx.x;
    int k  = t & (KK - 1);
    int bn = t >> 4;                    // b*NN + n
    int b  = bn / NN;

    float w[GG];
#pragma unroll
    for (int g = 0; g < GG; g++)
        w[g] = __half2float(g_w[((size_t)bn * GG + g) * KK + k]);

    int m = idx[(size_t)bn * KK + k];

    float* row = g_ct + ((size_t)b * NN + m) * CT_PAD;
    asm volatile("red.global.add.v4.f32 [%0], {%1, %2, %3, %4};"
                 :: "l"(row), "f"(w[0]), "f"(w[1]), "f"(w[2]), "f"(w[3])
                 : "memory");
    asm volatile("red.global.add.v4.f32 [%0], {%1, %2, %3, %4};"
                 :: "l"(row + 4), "f"(w[4]), "f"(w[5]), "f"(w[6]), "f"(w[7])
                 : "memory");
    atomicAdd(row + 8, w[8]);
}

// ---------------------------------------------------------------------------
// Finalize kernel: cent_t (B, N, 12) -> cent (B, G, N); coalesced writes.
// ---------------------------------------------------------------------------
__global__ void finalize_kernel(float* __restrict__ out) {
    int t = blockIdx.x * blockDim.x + threadIdx.x;   // b*NN + m
    int b = t / NN;
    int m = t % NN;
    const float* __restrict__ row = g_ct + (size_t)t * CT_PAD;
    float* __restrict__ cent = out + (size_t)BB * CC * NN + (size_t)b * GG * NN + m;
#pragma unroll
    for (int g = 0; g < GG; g++)
        cent[(size_t)g * NN] = row[g];
}

extern "C" void kernel_launch(void* const* d_in, const int* in_sizes, int n_in,
                              void* d_out, int out_size) {
    const float* qk  = (const float*)d_in[0];   // queryandkey (B, C, N) f32
    const float* val = (const float*)d_in[1];   // value       (B, C, N) f32
    const int*   idx = (const int*)d_in[2];     // idx_knn     (B, N, K) i32
    float* out = (float*)d_out;                 // [feat (B,C,N) | cent (B,G,N)]

    const int threads = 256;

    transpose_kernel<<<PTS / threads, threads>>>(qk, val);  // also zeroes g_ct
    attn_kernel<<<(int)(((size_t)BB * NN * JP * 8) / threads), threads>>>(qk, idx, out);
    scatter_kernel<<<(BB * NN * KK) / threads, threads>>>(idx);
    finalize_kernel<<<(BB * NN) / threads, threads>>>(out);
}